// round 1
// baseline (speedup 1.0000x reference)
#include <cuda_runtime.h>
#include <cstdint>

// InteractingSites: per-frame all-pairs soft-core Coulomb.
// B frames x S=128 sites, sites of frame f are contiguous [f*128, (f+1)*128).
// energy[f] = sum_{i<j} q_i q_j / sqrt(|p_i - p_j|^2 + EPS)
//
// One CTA per frame, 128 threads. Site table (x,y,z,q) in shared as float4,
// duplicated to 256 entries so the cyclic index i+d needs no modulo.
// Thread i covers cyclic offsets d=1..63 (all threads) + d=64 (threads 0..63):
// each unordered pair counted exactly once, perfectly balanced.

#define S_SITES 128
#define EPS_SOFT 1e-6f

__device__ __forceinline__ float fast_rsqrt(float x) {
    float r;
    asm("rsqrt.approx.f32 %0, %1;" : "=f"(r) : "f"(x));
    return r;
}

__global__ __launch_bounds__(S_SITES)
void interacting_sites_kernel(const float* __restrict__ positions,
                              const float* __restrict__ charges,
                              float* __restrict__ out) {
    __shared__ float4 site[2 * S_SITES];
    __shared__ float warp_sum[4];

    const int f = blockIdx.x;
    const int t = threadIdx.x;

    // Load this thread's site: positions is [N,3] row-major, charges [N].
    const int64_t base = (int64_t)f * S_SITES;
    const float* p = positions + (base + t) * 3;
    float4 v;
    v.x = p[0];
    v.y = p[1];
    v.z = p[2];
    v.w = charges[base + t];
    site[t] = v;
    site[t + S_SITES] = v;
    __syncthreads();

    const float px = v.x, py = v.y, pz = v.z, qi = v.w;
    float acc = 0.0f;

    // d = 1..63 for every thread
    #pragma unroll 7
    for (int d = 1; d < 64; ++d) {
        float4 s = site[t + d];
        float dx = px - s.x;
        float dy = py - s.y;
        float dz = pz - s.z;
        float r2 = fmaf(dx, dx, fmaf(dy, dy, fmaf(dz, dz, EPS_SOFT)));
        acc = fmaf(qi * s.w, fast_rsqrt(r2), acc);
    }

    // d = 64 only for threads 0..63 (each opposite pair once)
    if (t < 64) {
        float4 s = site[t + 64];
        float dx = px - s.x;
        float dy = py - s.y;
        float dz = pz - s.z;
        float r2 = fmaf(dx, dx, fmaf(dy, dy, fmaf(dz, dz, EPS_SOFT)));
        acc = fmaf(qi * s.w, fast_rsqrt(r2), acc);
    }

    // Reduce 128 threads -> 1 value
    #pragma unroll
    for (int o = 16; o > 0; o >>= 1)
        acc += __shfl_xor_sync(0xFFFFFFFFu, acc, o);

    const int warp = t >> 5;
    const int lane = t & 31;
    if (lane == 0) warp_sum[warp] = acc;
    __syncthreads();
    if (t == 0)
        out[f] = (warp_sum[0] + warp_sum[1]) + (warp_sum[2] + warp_sum[3]);
}

extern "C" void kernel_launch(void* const* d_in, const int* in_sizes, int n_in,
                              void* d_out, int out_size) {
    const float* positions = (const float*)d_in[0];  // [N,3] f32
    const float* charges   = (const float*)d_in[1];  // [N]   f32
    // d_in[2..4] = idx_i / idx_j / frames: implied by the dense per-frame
    // all-pairs structure, not needed.
    float* out = (float*)d_out;                      // [B]   f32

    const int num_frames = out_size;                 // B
    interacting_sites_kernel<<<num_frames, S_SITES>>>(positions, charges, out);
}